// round 1
// baseline (speedup 1.0000x reference)
#include <cuda_runtime.h>

// GAE backward scan.
// rewards: [T, B] f32, values: [T, B] f32, out: [T-1, B] f32
// delta[t] = r[t] + GAMMA*v[t+1] - v[t],  adv[t] = delta[t] + GL*adv[t+1]
// One thread per batch column; fully coalesced; unroll-by-8 with front-batched
// loads for MLP ~16 per warp.

#define T_LEN 1024
#define B_COLS 32768
#define TM1 1023           // output rows (t = 0 .. 1022)
#define GAMMA 0.99f
#define GL (0.99f * 0.95f)

__global__ __launch_bounds__(128) void gae_kernel(
    const float* __restrict__ rewards,
    const float* __restrict__ values,
    float* __restrict__ out)
{
    const int b = blockIdx.x * blockDim.x + threadIdx.x;
    if (b >= B_COLS) return;

    const float* r = rewards + b;
    const float* v = values + b;
    float* o = out + b;

    float adv = 0.0f;
    // v_next starts as v[T-1]
    float v_next = v[(size_t)TM1 * B_COLS];

    int t = TM1 - 1;  // 1022

    // Peel 7 iterations so the remaining 1016 is divisible by 8.
    #pragma unroll
    for (int i = 0; i < 7; ++i) {
        const size_t idx = (size_t)t * B_COLS;
        const float rt = r[idx];
        const float vt = v[idx];
        const float delta = fmaf(GAMMA, v_next, rt) - vt;
        adv = fmaf(GL, adv, delta);
        o[idx] = adv;
        v_next = vt;
        --t;
    }

    // Main loop: t goes 1015 .. 0 in blocks of 8 (127 blocks).
    for (; t >= 7; t -= 8) {
        float rt[8], vt[8];
        // Front-batch all 16 loads (independent of adv chain) -> MLP.
        #pragma unroll
        for (int i = 0; i < 8; ++i) {
            const size_t idx = (size_t)(t - i) * B_COLS;
            rt[i] = r[idx];
            vt[i] = v[idx];
        }
        #pragma unroll
        for (int i = 0; i < 8; ++i) {
            const float delta = fmaf(GAMMA, v_next, rt[i]) - vt[i];
            adv = fmaf(GL, adv, delta);
            o[(size_t)(t - i) * B_COLS] = adv;
            v_next = vt[i];
        }
    }
    // Remaining t = 6..0 (7 iterations)
    for (; t >= 0; --t) {
        const size_t idx = (size_t)t * B_COLS;
        const float rt = r[idx];
        const float vt = v[idx];
        const float delta = fmaf(GAMMA, v_next, rt) - vt;
        adv = fmaf(GL, adv, delta);
        o[idx] = adv;
        v_next = vt;
    }
}

extern "C" void kernel_launch(void* const* d_in, const int* in_sizes, int n_in,
                              void* d_out, int out_size) {
    const float* rewards = (const float*)d_in[0];
    const float* values  = (const float*)d_in[1];
    float* out = (float*)d_out;

    const int threads = 128;
    const int blocks = B_COLS / threads;  // 256
    gae_kernel<<<blocks, threads>>>(rewards, values, out);
}